// round 10
// baseline (speedup 1.0000x reference)
#include <cuda_runtime.h>
#include <cuda_bf16.h>

#define B_CONST 32
#define L_CONST 256
#define H_CONST 512
#define ROWS_PER_WARP   8
#define WARPS_PER_BLOCK 8
#define ROWS_PER_BLOCK  (ROWS_PER_WARP * WARPS_PER_BLOCK)   // 64

// Single fused kernel. Each block serves one batch b and 64 consecutive output
// rows. Prologue: recompute the per-batch inclusive cumsum of durations (1KB,
// L2-hot) with a warp-shuffle scan into shared. Each warp handles 8
// consecutive rows: binary-search the source index ONCE (9 steps, fully
// resolved), then advance monotonically (csum is sorted) with a short linear
// walk per row. The 2KB source row is reloaded only when the index changes
// (~87% reuse). Streaming stores (__stcs) keep x resident in L2. Rows past
// total are zeroed; mask written by the first 64 threads.
__global__ void __launch_bounds__(256) fused_kernel(
    const float4* __restrict__ x4,       // [B, L, 128]
    const int*    __restrict__ dur,      // [B, L]
    float4*       __restrict__ out4,     // [B, T, 128]
    float*        __restrict__ out_mask, // [B, T]
    int T)
{
    __shared__ int s_csum[L_CONST];
    __shared__ int s_wsum[8];

    int b    = blockIdx.y;
    int tid  = threadIdx.x;
    int lane = tid & 31;
    int w    = tid >> 5;

    // ---- per-batch scan of durations into s_csum (inclusive) ----
    int d = dur[b * L_CONST + tid];
    int v = d;
    #pragma unroll
    for (int off = 1; off < 32; off <<= 1) {
        int n = __shfl_up_sync(0xFFFFFFFFu, v, off);
        if (lane >= off) v += n;
    }
    if (lane == 31) s_wsum[w] = v;
    __syncthreads();
    if (w == 0) {
        int ws = (lane < 8) ? s_wsum[lane] : 0;
        #pragma unroll
        for (int off = 1; off < 8; off <<= 1) {
            int n = __shfl_up_sync(0xFFFFFFFFu, ws, off);
            if (lane >= off) ws += n;
        }
        if (lane < 8) s_wsum[lane] = ws;
    }
    __syncthreads();
    int base = (w > 0) ? s_wsum[w - 1] : 0;
    s_csum[tid] = base + v;
    __syncthreads();

    int total    = s_csum[L_CONST - 1];
    int t0_block = blockIdx.x * ROWS_PER_BLOCK;

    // ---- mask for this block's 64 rows ----
    if (tid < ROWS_PER_BLOCK) {
        int tm = t0_block + tid;
        if (tm < T)
            out_mask[(size_t)b * T + tm] = (tm < total) ? 1.0f : 0.0f;
    }

    // ---- expand: one warp per 8 consecutive rows ----
    int t0 = t0_block + w * ROWS_PER_WARP;
    if (t0 >= T) return;

    // searchsorted(csum, t0, 'right') once: first l with csum[l] > t0.
    // [0,256) needs NINE bisection steps to fully resolve (lo==hi).
    int idx = 0;
    if (t0 < total) {
        int lo = 0, hi = L_CONST;
        #pragma unroll
        for (int step = 0; step < 9; ++step) {
            int mid = (lo + hi) >> 1;
            if (s_csum[mid] <= t0) lo = mid + 1; else hi = mid;
        }
        idx = lo;                         // <= L-1 because csum[L-1]=total > t0
    }

    const float4 z = make_float4(0.f, 0.f, 0.f, 0.f);
    float4 v0 = z, v1 = z, v2 = z, v3 = z;
    int cur = -2;

    float4* dp = out4 + ((size_t)b * T + t0) * 128 + lane;

    #pragma unroll
    for (int r = 0; r < ROWS_PER_WARP; ++r) {
        int t = t0 + r;
        if (t >= T) break;

        int want;
        if (t >= total) {
            want = -1;
        } else {
            // monotone advance: csum sorted, t increases by 1 per row
            while (s_csum[idx] <= t) ++idx;   // terminates: csum[L-1] > t
            want = idx;
        }

        if (want != cur) {
            if (want >= 0) {
                const float4* s = x4 + ((size_t)b * L_CONST + want) * 128 + lane;
                v0 = __ldg(s);
                v1 = __ldg(s + 32);
                v2 = __ldg(s + 64);
                v3 = __ldg(s + 96);
            } else {
                v0 = z; v1 = z; v2 = z; v3 = z;
            }
            cur = want;
        }

        __stcs(dp,      v0);
        __stcs(dp + 32, v1);
        __stcs(dp + 64, v2);
        __stcs(dp + 96, v3);
        dp += 128;
    }
}

extern "C" void kernel_launch(void* const* d_in, const int* in_sizes, int n_in,
                              void* d_out, int out_size) {
    const float* x;
    const int*   dur;
    if (in_sizes[0] == B_CONST * L_CONST) {
        dur = (const int*)d_in[0];
        x   = (const float*)d_in[1];
    } else {
        x   = (const float*)d_in[0];
        dur = (const int*)d_in[1];
    }

    int T = out_size / (B_CONST * (H_CONST + 1));

    float* out      = (float*)d_out;
    float* out_mask = out + (size_t)B_CONST * T * H_CONST;

    dim3 grid((T + ROWS_PER_BLOCK - 1) / ROWS_PER_BLOCK, B_CONST);
    fused_kernel<<<grid, 256>>>(
        (const float4*)x, dur, (float4*)out, out_mask, T);
}

// round 11
// speedup vs baseline: 1.0531x; 1.0531x over previous
#include <cuda_runtime.h>
#include <cuda_bf16.h>

#define B_CONST 32
#define L_CONST 256
#define H_CONST 512
#define ROWS_PER_WARP   4
#define WARPS_PER_BLOCK 8
#define ROWS_PER_BLOCK  (ROWS_PER_WARP * WARPS_PER_BLOCK)   // 32

// Single fused kernel. Each block serves one batch b and 32 consecutive output
// rows (R9 grid shape: finer tail granularity, best measured total). Prologue:
// recompute the per-batch inclusive cumsum of durations (1KB, L2-hot) with a
// warp-shuffle scan into shared. Each warp handles 4 consecutive rows: ONE
// 9-step binary search for the first row, then a monotone linear walk for the
// rest (R10 index logic: ~6x fewer shared-mem probes). The 2KB source row is
// reloaded only when the index changes (~87% reuse). Streaming stores (__stcs)
// keep x resident in L2. Rows past total are zeroed; mask written in-kernel.
__global__ void __launch_bounds__(256) fused_kernel(
    const float4* __restrict__ x4,       // [B, L, 128]
    const int*    __restrict__ dur,      // [B, L]
    float4*       __restrict__ out4,     // [B, T, 128]
    float*        __restrict__ out_mask, // [B, T]
    int T)
{
    __shared__ int s_csum[L_CONST];
    __shared__ int s_wsum[8];

    int b    = blockIdx.y;
    int tid  = threadIdx.x;
    int lane = tid & 31;
    int w    = tid >> 5;

    // ---- per-batch scan of durations into s_csum (inclusive) ----
    int d = dur[b * L_CONST + tid];
    int v = d;
    #pragma unroll
    for (int off = 1; off < 32; off <<= 1) {
        int n = __shfl_up_sync(0xFFFFFFFFu, v, off);
        if (lane >= off) v += n;
    }
    if (lane == 31) s_wsum[w] = v;
    __syncthreads();
    if (w == 0) {
        int ws = (lane < 8) ? s_wsum[lane] : 0;
        #pragma unroll
        for (int off = 1; off < 8; off <<= 1) {
            int n = __shfl_up_sync(0xFFFFFFFFu, ws, off);
            if (lane >= off) ws += n;
        }
        if (lane < 8) s_wsum[lane] = ws;
    }
    __syncthreads();
    int base = (w > 0) ? s_wsum[w - 1] : 0;
    s_csum[tid] = base + v;
    __syncthreads();

    int total    = s_csum[L_CONST - 1];
    int t0_block = blockIdx.x * ROWS_PER_BLOCK;

    // ---- mask for this block's 32 rows ----
    if (tid < ROWS_PER_BLOCK) {
        int tm = t0_block + tid;
        if (tm < T)
            out_mask[(size_t)b * T + tm] = (tm < total) ? 1.0f : 0.0f;
    }

    // ---- expand: one warp per 4 consecutive rows ----
    int t0 = t0_block + w * ROWS_PER_WARP;
    if (t0 >= T) return;

    // searchsorted(csum, t0, 'right') once: first l with csum[l] > t0.
    // [0,256) needs NINE bisection steps to fully resolve (lo==hi).
    int idx = 0;
    if (t0 < total) {
        int lo = 0, hi = L_CONST;
        #pragma unroll
        for (int step = 0; step < 9; ++step) {
            int mid = (lo + hi) >> 1;
            if (s_csum[mid] <= t0) lo = mid + 1; else hi = mid;
        }
        idx = lo;                        // <= L-1 since csum[L-1] = total > t0
    }

    const float4 z = make_float4(0.f, 0.f, 0.f, 0.f);
    float4 v0 = z, v1 = z, v2 = z, v3 = z;
    int cur = -2;

    float4* dp = out4 + ((size_t)b * T + t0) * 128 + lane;

    #pragma unroll
    for (int r = 0; r < ROWS_PER_WARP; ++r) {
        int t = t0 + r;
        if (t >= T) break;

        int want;
        if (t >= total) {
            want = -1;
        } else {
            // monotone advance: csum sorted, t increases by 1 per row
            while (s_csum[idx] <= t) ++idx;   // terminates: csum[L-1] > t
            want = idx;
        }

        if (want != cur) {
            if (want >= 0) {
                const float4* s = x4 + ((size_t)b * L_CONST + want) * 128 + lane;
                v0 = __ldg(s);
                v1 = __ldg(s + 32);
                v2 = __ldg(s + 64);
                v3 = __ldg(s + 96);
            } else {
                v0 = z; v1 = z; v2 = z; v3 = z;
            }
            cur = want;
        }

        __stcs(dp,      v0);
        __stcs(dp + 32, v1);
        __stcs(dp + 64, v2);
        __stcs(dp + 96, v3);
        dp += 128;
    }
}

extern "C" void kernel_launch(void* const* d_in, const int* in_sizes, int n_in,
                              void* d_out, int out_size) {
    const float* x;
    const int*   dur;
    if (in_sizes[0] == B_CONST * L_CONST) {
        dur = (const int*)d_in[0];
        x   = (const float*)d_in[1];
    } else {
        x   = (const float*)d_in[0];
        dur = (const int*)d_in[1];
    }

    int T = out_size / (B_CONST * (H_CONST + 1));

    float* out      = (float*)d_out;
    float* out_mask = out + (size_t)B_CONST * T * H_CONST;

    dim3 grid((T + ROWS_PER_BLOCK - 1) / ROWS_PER_BLOCK, B_CONST);
    fused_kernel<<<grid, 256>>>(
        (const float4*)x, dur, (float4*)out, out_mask, T);
}